// round 4
// baseline (speedup 1.0000x reference)
#include <cuda_runtime.h>

#define T_ 512
#define K_ 8
#define D_ 8
#define NB 4

static constexpr int TK = T_ * K_;

// Per-(t,k) precomputed parameters (device scratch — no allocation)
__device__ float g_Q[TK * 64];     // [tk][i*8+j]  Q = 2*inv(I+A) - I
__device__ float g_bias[TK * 8];   // [tk][j]      = -(center . Q)_j
__device__ float g_c1[TK * 8];     // [tk][d]      = -0.5/var * log2(e)
__device__ float g_lc0[TK * 8];    // [tk][d]      = -0.5*ln(2*pi*var) * log2(e)
__device__ float g_w[TK];          // [t][k]       softmax weights

// ---------- packed f32x2 helpers ----------
typedef unsigned long long u64_t;

static __device__ __forceinline__ u64_t pk2(float lo, float hi) {
    u64_t r;
    asm("mov.b64 %0, {%1, %2};" : "=l"(r) : "f"(lo), "f"(hi));
    return r;
}
static __device__ __forceinline__ void upk2(u64_t v, float& lo, float& hi) {
    asm("mov.b64 {%0, %1}, %2;" : "=f"(lo), "=f"(hi) : "l"(v));
}
static __device__ __forceinline__ u64_t fma2_(u64_t a, u64_t b, u64_t c) {
    u64_t d;
    asm("fma.rn.f32x2 %0, %1, %2, %3;" : "=l"(d) : "l"(a), "l"(b), "l"(c));
    return d;
}
static __device__ __forceinline__ u64_t mul2_(u64_t a, u64_t b) {
    u64_t d;
    asm("mul.rn.f32x2 %0, %1, %2;" : "=l"(d) : "l"(a), "l"(b));
    return d;
}
static __device__ __forceinline__ u64_t add2_(u64_t a, u64_t b) {
    u64_t d;
    asm("add.rn.f32x2 %0, %1, %2;" : "=l"(d) : "l"(a), "l"(b));
    return d;
}
static __device__ __forceinline__ float ex2_(float a) {
    float r;
    asm("ex2.approx.f32 %0, %1;" : "=f"(r) : "f"(a));
    return r;
}

// ============================================================================
// Precompute. One thread per (t,k). Fully unrolled, static indexing only
// (everything stays in registers — the round-2 version spilled to local
// because of dynamic pivot indexing).
// Q = (I-A)(I+A)^-1 = 2*(I+A)^-1 - I   (commuting rational functions of A).
// (I+A) has positive-definite symmetric part -> pivot-free GJ is stable.
// ============================================================================
__global__ void __launch_bounds__(64)
precompute_kernel(const float* __restrict__ centers,
                  const float* __restrict__ wlog,
                  const float* __restrict__ logvar,
                  const float* __restrict__ cov)
{
    const int tk = blockIdx.x * blockDim.x + threadIdx.x;

    // Softmax of clipped weight logits (one thread per t)
    if (tk < T_) {
        float l[K_];
        float mx = -1e30f;
        #pragma unroll
        for (int k = 0; k < K_; k++) {
            float v = wlog[tk * K_ + k];
            v = fminf(fmaxf(v, -3.5f), 3.5f);
            l[k] = v;
            mx = fmaxf(mx, v);
        }
        float s = 0.f;
        #pragma unroll
        for (int k = 0; k < K_; k++) { l[k] = __expf(l[k] - mx); s += l[k]; }
        float inv = 1.0f / s;
        #pragma unroll
        for (int k = 0; k < K_; k++) g_w[tk * K_ + k] = l[k] * inv;
    }

    if (tk >= TK) return;

    // ---- build M = I + A directly (A antisym from cov_param) ----
    const float* v = cov + tk * 28;
    float flat[56];
    #pragma unroll
    for (int i = 0; i < 28; i++) { flat[i] = v[i]; flat[28 + i] = v[27 - i]; }

    float M[8][8];
    #pragma unroll
    for (int r = 0; r < 8; r++) {
        #pragma unroll
        for (int c = 0; c < 8; c++) {
            // strict-upper value of 'a' at (r,c): flat[8r+c] if c>r (index <56 always)
            float ut_rc = (c > r) ? flat[8 * r + c] : 0.f;
            float ut_cr = (r > c) ? flat[8 * c + r] : 0.f;
            float A_rc = 0.5f * (ut_cr - ut_rc);
            M[r][c] = A_rc + ((r == c) ? 1.f : 0.f);
        }
    }

    // ---- in-place Gauss-Jordan inverse, no pivoting, fully unrolled ----
    #pragma unroll
    for (int col = 0; col < 8; col++) {
        float p = 1.0f / M[col][col];
        M[col][col] = p;
        #pragma unroll
        for (int j = 0; j < 8; j++)
            if (j != col) M[col][j] *= p;
        #pragma unroll
        for (int r = 0; r < 8; r++) {
            if (r == col) continue;
            float f = M[r][col];
            #pragma unroll
            for (int j = 0; j < 8; j++)
                if (j != col) M[r][j] = fmaf(-f, M[col][j], M[r][j]);
            M[r][col] = -f * p;
        }
    }

    // ---- Q = 2*inv(I+A) - I ----
    float* Qo = g_Q + tk * 64;
    #pragma unroll
    for (int r = 0; r < 8; r++) {
        #pragma unroll
        for (int c = 0; c < 8; c++) {
            float q = 2.0f * M[r][c] - ((r == c) ? 1.f : 0.f);
            M[r][c] = q;          // reuse M as Q
            Qo[r * 8 + c] = q;
        }
    }

    // bias_j = -(center . Q)_j
    const float* cc = centers + tk * 8;
    #pragma unroll
    for (int j = 0; j < 8; j++) {
        float s = 0.f;
        #pragma unroll
        for (int i = 0; i < 8; i++) s = fmaf(cc[i], M[i][j], s);
        g_bias[tk * 8 + j] = -s;
    }

    // variance terms, log2e folded in so the main kernel uses raw ex2
    const float LOG2PI = 1.8378770664093453f;
    const float LOG2E  = 1.4426950408889634f;
    #pragma unroll
    for (int d = 0; d < 8; d++) {
        float lv = logvar[tk * 8 + d];
        lv = fminf(fmaxf(lv, -3.5f), 3.5f);
        g_c1[tk * 8 + d]  = -0.5f * expf(-lv) * LOG2E;
        g_lc0[tk * 8 + d] = -0.5f * (LOG2PI + lv) * LOG2E;
    }
}

// ============================================================================
// Main kernel: one block per (b-chunk, t); each thread computes NB=4 outputs.
// p[b,t] = sum_k w[t,k] * prod_d ( ex2(c1'*xt_d^2 + lc0') + 1e-7 )
// xt = x . Q + bias.  Processed in two j-halves to keep xt live regs at 16.
// Product carried as packed f32x2 pair at 2^40-per-half scale (2^80 total).
// ============================================================================
__global__ void __launch_bounds__(128, 6)
pecd_main_kernel(const float* __restrict__ x, float* __restrict__ out)
{
    const int t   = blockIdx.y;
    const int tid = threadIdx.x;

    __shared__ __align__(16) float sQ[K_ * 64];
    __shared__ __align__(16) float sB[K_ * 8];
    __shared__ __align__(16) float sC[K_ * 8];
    __shared__ __align__(16) float sL[K_ * 8];
    __shared__ float sW[K_];

    {
        const float* gq = g_Q + t * (K_ * 64);
        for (int i = tid; i < K_ * 64; i += 128) sQ[i] = gq[i];
        if (tid < 64) {
            sB[tid] = g_bias[t * 64 + tid];
            sC[tid] = g_c1[t * 64 + tid];
            sL[tid] = g_lc0[t * 64 + tid];
        }
        if (tid < K_) sW[tid] = g_w[t * K_ + tid];
    }
    __syncthreads();

    const int b0 = blockIdx.x * (128 * NB) + tid;

    // x rows: one (b,t) row = 8 floats = 32B, fully-used sectors
    float xr[NB][8];
    const float4* x4 = reinterpret_cast<const float4*>(x);
    #pragma unroll
    for (int ib = 0; ib < NB; ib++) {
        const int b = b0 + ib * 128;
        const float4 p0 = x4[(size_t)(b * T_ + t) * 2 + 0];
        const float4 p1 = x4[(size_t)(b * T_ + t) * 2 + 1];
        xr[ib][0] = p0.x; xr[ib][1] = p0.y; xr[ib][2] = p0.z; xr[ib][3] = p0.w;
        xr[ib][4] = p1.x; xr[ib][5] = p1.y; xr[ib][6] = p1.z; xr[ib][7] = p1.w;
    }

    const u64_t EPS2      = pk2(1e-7f, 1e-7f);
    const u64_t PROD_INIT = pk2(0x1p40f, 0x1p40f);   // 2^40 per half -> 2^80 total

    float acc[NB];
    #pragma unroll
    for (int ib = 0; ib < NB; ib++) acc[ib] = 0.f;

    #pragma unroll
    for (int k = 0; k < K_; k++) {
        const float4* q4 = reinterpret_cast<const float4*>(&sQ[k * 64]);
        const float4* b4 = reinterpret_cast<const float4*>(&sB[k * 8]);
        const float4* c4 = reinterpret_cast<const float4*>(&sC[k * 8]);
        const float4* l4 = reinterpret_cast<const float4*>(&sL[k * 8]);
        const float wk = sW[k];

        u64_t prod2[NB];
        #pragma unroll
        for (int ib = 0; ib < NB; ib++) prod2[ib] = PROD_INIT;

        #pragma unroll
        for (int h = 0; h < 2; h++) {               // j-half: dims [4h, 4h+4)
            const float4 bb = b4[h];
            const u64_t bias0 = pk2(bb.x, bb.y), bias1 = pk2(bb.z, bb.w);
            const float4 cc = c4[h];
            const u64_t cp0 = pk2(cc.x, cc.y), cp1 = pk2(cc.z, cc.w);
            const float4 ll = l4[h];
            const u64_t lp0 = pk2(ll.x, ll.y), lp1 = pk2(ll.z, ll.w);

            u64_t xt0[NB], xt1[NB];
            #pragma unroll
            for (int ib = 0; ib < NB; ib++) { xt0[ib] = bias0; xt1[ib] = bias1; }

            #pragma unroll
            for (int i = 0; i < 8; i++) {
                const float4 q = q4[2 * i + h];
                const u64_t q0 = pk2(q.x, q.y), q1 = pk2(q.z, q.w);
                #pragma unroll
                for (int ib = 0; ib < NB; ib++) {
                    const u64_t xi = pk2(xr[ib][i], xr[ib][i]);
                    xt0[ib] = fma2_(xi, q0, xt0[ib]);
                    xt1[ib] = fma2_(xi, q1, xt1[ib]);
                }
            }

            #pragma unroll
            for (int ib = 0; ib < NB; ib++) {
                const u64_t s0 = mul2_(xt0[ib], xt0[ib]);
                const u64_t a0 = fma2_(cp0, s0, lp0);
                const u64_t s1 = mul2_(xt1[ib], xt1[ib]);
                const u64_t a1 = fma2_(cp1, s1, lp1);
                float e0, e1, e2, e3;
                upk2(a0, e0, e1);
                upk2(a1, e2, e3);
                e0 = ex2_(e0); e1 = ex2_(e1); e2 = ex2_(e2); e3 = ex2_(e3);
                const u64_t g01 = add2_(pk2(e0, e1), EPS2);
                const u64_t g23 = add2_(pk2(e2, e3), EPS2);
                prod2[ib] = mul2_(prod2[ib], g01);
                prod2[ib] = mul2_(prod2[ib], g23);
            }
        }

        #pragma unroll
        for (int ib = 0; ib < NB; ib++) {
            float plo, phi;
            upk2(prod2[ib], plo, phi);
            acc[ib] = fmaf(wk, plo * phi, acc[ib]);
        }
    }

    #pragma unroll
    for (int ib = 0; ib < NB; ib++) {
        const int b = b0 + ib * 128;
        out[(size_t)b * T_ + t] = acc[ib] * 0x1p-80f;
    }
}

// ============================================================================
extern "C" void kernel_launch(void* const* d_in, const int* in_sizes, int n_in,
                              void* d_out, int out_size)
{
    const float* x       = (const float*)d_in[0];  // [B, T, D]
    const float* centers = (const float*)d_in[1];  // [T, K, D]
    const float* wlog    = (const float*)d_in[2];  // [T, K]
    const float* logvar  = (const float*)d_in[3];  // [T, K, D]
    const float* cov     = (const float*)d_in[4];  // [T, K, 28]

    const int B = in_sizes[0] / (T_ * D_);         // 2048

    precompute_kernel<<<TK / 64, 64>>>(centers, wlog, logvar, cov);

    dim3 grid(B / (128 * NB), T_);                 // (4, 512)
    pecd_main_kernel<<<grid, 128>>>(x, (float*)d_out);
}

// round 8
// speedup vs baseline: 1.6106x; 1.6106x over previous
#include <cuda_runtime.h>

#define T_ 512
#define K_ 8
#define D_ 8
#define NB 4

static constexpr int TK = T_ * K_;

// Per-(t,k) precomputed parameters (device scratch — no allocation)
__device__ float g_Q[TK * 64];     // [tk][i*8+j]  Q = 2*inv(I+A) - I
__device__ float g_bias[TK * 8];   // [tk][j]      = -(center . Q)_j
__device__ float g_c1[TK * 8];     // [tk][d]      = -0.5/var * log2(e)
__device__ float g_lc0[TK * 8];    // [tk][d]      = -0.5*ln(2*pi*var) * log2(e)
__device__ float g_w[TK];          // [t][k]       softmax weights

// ---------- packed f32x2 helpers ----------
typedef unsigned long long u64_t;

static __device__ __forceinline__ u64_t pk2(float lo, float hi) {
    u64_t r;
    asm("mov.b64 %0, {%1, %2};" : "=l"(r) : "f"(lo), "f"(hi));
    return r;
}
static __device__ __forceinline__ void upk2(u64_t v, float& lo, float& hi) {
    asm("mov.b64 {%0, %1}, %2;" : "=f"(lo), "=f"(hi) : "l"(v));
}
static __device__ __forceinline__ u64_t fma2_(u64_t a, u64_t b, u64_t c) {
    u64_t d;
    asm("fma.rn.f32x2 %0, %1, %2, %3;" : "=l"(d) : "l"(a), "l"(b), "l"(c));
    return d;
}
static __device__ __forceinline__ u64_t mul2_(u64_t a, u64_t b) {
    u64_t d;
    asm("mul.rn.f32x2 %0, %1, %2;" : "=l"(d) : "l"(a), "l"(b));
    return d;
}
static __device__ __forceinline__ float ex2_(float a) {
    float r;
    asm("ex2.approx.f32 %0, %1;" : "=f"(r) : "f"(a));
    return r;
}

// ============================================================================
// Precompute, warp-parallel: 8 threads per (t,k), one Gauss-Jordan row each.
// Pivot rows exchanged with shfl (width 8); bias via butterfly reduction.
// Q = (I-A)(I+A)^-1 = 2*(I+A)^-1 - I  (commuting rational functions of A);
// (I+A) has positive-definite symmetric part -> pivot-free GJ is stable.
// ============================================================================
__global__ void __launch_bounds__(256)
precompute_kernel(const float* __restrict__ centers,
                  const float* __restrict__ wlog,
                  const float* __restrict__ logvar,
                  const float* __restrict__ cov)
{
    const int gtid = blockIdx.x * 256 + threadIdx.x;
    const int tk   = gtid >> 3;     // 0 .. TK-1
    const int r    = gtid & 7;      // row owned by this thread
    if (tk >= TK) return;

    // Softmax of clipped weight logits (one lane per t, t == tk for tk < T_)
    if (tk < T_ && r == 0) {
        const int t = tk;
        float l[K_];
        float mx = -1e30f;
        #pragma unroll
        for (int k = 0; k < K_; k++) {
            float v = wlog[t * K_ + k];
            v = fminf(fmaxf(v, -3.5f), 3.5f);
            l[k] = v;
            mx = fmaxf(mx, v);
        }
        float s = 0.f;
        #pragma unroll
        for (int k = 0; k < K_; k++) { l[k] = __expf(l[k] - mx); s += l[k]; }
        float inv = 1.0f / s;
        #pragma unroll
        for (int k = 0; k < K_; k++) g_w[t * K_ + k] = l[k] * inv;
    }

    // ---- build row r of M = I + A  (A antisym from 28 cov params) ----
    // flat[j] = v[j] for j<28, v[55-j] for 28<=j<56 (tf concat [v, v[::-1]])
    const float* v = cov + tk * 28;
    float Mrow[8];
    #pragma unroll
    for (int c = 0; c < 8; c++) {
        float ut_rc = 0.f, ut_cr = 0.f;
        if (c > r) { int j = 8 * r + c; ut_rc = (j < 28) ? v[j] : v[55 - j]; }
        if (r > c) { int j = 8 * c + r; ut_cr = (j < 28) ? v[j] : v[55 - j]; }
        Mrow[c] = 0.5f * (ut_cr - ut_rc) + ((r == c) ? 1.f : 0.f);
    }

    // ---- distributed in-place Gauss-Jordan inverse, no pivoting ----
    #pragma unroll
    for (int col = 0; col < 8; col++) {
        float prow[8];
        #pragma unroll
        for (int j = 0; j < 8; j++)
            prow[j] = __shfl_sync(0xffffffffu, Mrow[j], col, 8);
        const float p = 1.0f / prow[col];
        if (r == col) {
            #pragma unroll
            for (int j = 0; j < 8; j++)
                Mrow[j] = (j == col) ? p : prow[j] * p;
        } else {
            const float f = Mrow[col];
            #pragma unroll
            for (int j = 0; j < 8; j++)
                if (j != col) Mrow[j] = fmaf(-f, prow[j] * p, Mrow[j]);
            Mrow[col] = -f * p;
        }
    }

    // ---- Q row = 2*inv(I+A) row - I row ----
    float Qrow[8];
    #pragma unroll
    for (int j = 0; j < 8; j++) {
        Qrow[j] = 2.0f * Mrow[j] - ((r == j) ? 1.f : 0.f);
        g_Q[tk * 64 + r * 8 + j] = Qrow[j];
    }

    // ---- bias_j = -(center . Q)_j : butterfly-reduce c_r * Qrow over lanes ----
    {
        const float cr = centers[tk * 8 + r];
        float s[8];
        #pragma unroll
        for (int j = 0; j < 8; j++) s[j] = cr * Qrow[j];
        #pragma unroll
        for (int m = 1; m < 8; m <<= 1) {
            #pragma unroll
            for (int j = 0; j < 8; j++)
                s[j] += __shfl_xor_sync(0xffffffffu, s[j], m, 8);
        }
        g_bias[tk * 8 + r] = -s[r];   // lane r writes element r
    }

    // ---- variance terms, log2(e) folded in so main kernel uses raw ex2 ----
    {
        const float LOG2PI = 1.8378770664093453f;
        const float LOG2E  = 1.4426950408889634f;
        float lv = logvar[tk * 8 + r];
        lv = fminf(fmaxf(lv, -3.5f), 3.5f);
        g_c1[tk * 8 + r]  = -0.5f * expf(-lv) * LOG2E;
        g_lc0[tk * 8 + r] = -0.5f * (LOG2PI + lv) * LOG2E;
    }
}

// ============================================================================
// Main kernel (round-2 structure preserved): one block per (b-chunk, t);
// each thread computes NB=4 outputs.
// p[b,t] = sum_k w[t,k] * prod_d ( ex2(c1'*xt_d^2 + lc0') + 1e-7 )
// xt = x . Q + bias, packed fma.rn.f32x2 over j-pairs (x-dup packs hoisted
// by ptxas — do NOT restructure, see round-3 post-mortem).
// Product guarded with 2^80 scale against intermediate underflow.
// ============================================================================
__global__ void __launch_bounds__(128)
pecd_main_kernel(const float* __restrict__ x, float* __restrict__ out)
{
    const int t   = blockIdx.y;
    const int tid = threadIdx.x;

    __shared__ __align__(16) float sQ[K_ * 64];
    __shared__ __align__(16) float sB[K_ * 8];
    __shared__ __align__(16) float sC[K_ * 8];
    __shared__ __align__(16) float sL[K_ * 8];
    __shared__ float sW[K_];

    {
        const float* gq = g_Q + t * (K_ * 64);
        for (int i = tid; i < K_ * 64; i += 128) sQ[i] = gq[i];
        if (tid < 64) {
            sB[tid] = g_bias[t * 64 + tid];
            sC[tid] = g_c1[t * 64 + tid];
            sL[tid] = g_lc0[t * 64 + tid];
        }
        if (tid < K_) sW[tid] = g_w[t * K_ + tid];
    }
    __syncthreads();

    const int b0 = blockIdx.x * (128 * NB) + tid;

    // load x rows: each (b,t) row is 8 floats = one aligned 32B sector
    float xr[NB][8];
    const float4* x4 = reinterpret_cast<const float4*>(x);
    #pragma unroll
    for (int ib = 0; ib < NB; ib++) {
        const int b = b0 + ib * 128;
        const float4 p0 = x4[(size_t)(b * T_ + t) * 2 + 0];
        const float4 p1 = x4[(size_t)(b * T_ + t) * 2 + 1];
        xr[ib][0] = p0.x; xr[ib][1] = p0.y; xr[ib][2] = p0.z; xr[ib][3] = p0.w;
        xr[ib][4] = p1.x; xr[ib][5] = p1.y; xr[ib][6] = p1.z; xr[ib][7] = p1.w;
    }

    float acc[NB];
    #pragma unroll
    for (int ib = 0; ib < NB; ib++) acc[ib] = 0.f;

    #pragma unroll
    for (int k = 0; k < K_; k++) {
        const float4* q4 = reinterpret_cast<const float4*>(&sQ[k * 64]);

        // bias pairs
        const float4 bb0 = reinterpret_cast<const float4*>(&sB[k * 8])[0];
        const float4 bb1 = reinterpret_cast<const float4*>(&sB[k * 8])[1];
        u64_t bias01 = pk2(bb0.x, bb0.y), bias23 = pk2(bb0.z, bb0.w);
        u64_t bias45 = pk2(bb1.x, bb1.y), bias67 = pk2(bb1.z, bb1.w);

        u64_t xt[NB][4];
        #pragma unroll
        for (int ib = 0; ib < NB; ib++) {
            xt[ib][0] = bias01; xt[ib][1] = bias23;
            xt[ib][2] = bias45; xt[ib][3] = bias67;
        }

        // xt_j += sum_i x_i * Q[i][j]   (packed over j-pairs)
        #pragma unroll
        for (int i = 0; i < 8; i++) {
            const float4 qa = q4[2 * i + 0];
            const float4 qb = q4[2 * i + 1];
            const u64_t q01 = pk2(qa.x, qa.y), q23 = pk2(qa.z, qa.w);
            const u64_t q45 = pk2(qb.x, qb.y), q67 = pk2(qb.z, qb.w);
            #pragma unroll
            for (int ib = 0; ib < NB; ib++) {
                const u64_t xi = pk2(xr[ib][i], xr[ib][i]);
                xt[ib][0] = fma2_(xi, q01, xt[ib][0]);
                xt[ib][1] = fma2_(xi, q23, xt[ib][1]);
                xt[ib][2] = fma2_(xi, q45, xt[ib][2]);
                xt[ib][3] = fma2_(xi, q67, xt[ib][3]);
            }
        }

        // gaussian product (c1/lc0 already carry log2(e) -> raw ex2)
        const float4 c0 = reinterpret_cast<const float4*>(&sC[k * 8])[0];
        const float4 c1 = reinterpret_cast<const float4*>(&sC[k * 8])[1];
        const float4 l0 = reinterpret_cast<const float4*>(&sL[k * 8])[0];
        const float4 l1 = reinterpret_cast<const float4*>(&sL[k * 8])[1];
        u64_t cp[4], lp[4];
        cp[0] = pk2(c0.x, c0.y); cp[1] = pk2(c0.z, c0.w);
        cp[2] = pk2(c1.x, c1.y); cp[3] = pk2(c1.z, c1.w);
        lp[0] = pk2(l0.x, l0.y); lp[1] = pk2(l0.z, l0.w);
        lp[2] = pk2(l1.x, l1.y); lp[3] = pk2(l1.z, l1.w);

        const float wk = sW[k];

        #pragma unroll
        for (int ib = 0; ib < NB; ib++) {
            float m[4];
            #pragma unroll
            for (int jp = 0; jp < 4; jp++) {
                const u64_t t2 = mul2_(xt[ib][jp], xt[ib][jp]);
                const u64_t ar = fma2_(cp[jp], t2, lp[jp]);
                float a0, a1;
                upk2(ar, a0, a1);
                const float g0 = ex2_(a0) + 1e-7f;
                const float g1 = ex2_(a1) + 1e-7f;
                m[jp] = g0 * g1;
            }
            // tree product with 2^80 underflow guard (undone at store)
            const float mm01 = m[0] * m[1];
            const float mm23 = m[2] * m[3];
            const float prod = (mm01 * 0x1p80f) * mm23;
            acc[ib] = fmaf(wk, prod, acc[ib]);
        }
    }

    #pragma unroll
    for (int ib = 0; ib < NB; ib++) {
        const int b = b0 + ib * 128;
        out[(size_t)b * T_ + t] = acc[ib] * 0x1p-80f;
    }
}

// ============================================================================
extern "C" void kernel_launch(void* const* d_in, const int* in_sizes, int n_in,
                              void* d_out, int out_size)
{
    const float* x       = (const float*)d_in[0];  // [B, T, D]
    const float* centers = (const float*)d_in[1];  // [T, K, D]
    const float* wlog    = (const float*)d_in[2];  // [T, K]
    const float* logvar  = (const float*)d_in[3];  // [T, K, D]
    const float* cov     = (const float*)d_in[4];  // [T, K, 28]

    const int B = in_sizes[0] / (T_ * D_);         // 2048

    precompute_kernel<<<(TK * 8) / 256, 256>>>(centers, wlog, logvar, cov);

    dim3 grid(B / (128 * NB), T_);                 // (4, 512)
    pecd_main_kernel<<<grid, 128>>>(x, (float*)d_out);
}

// round 11
// speedup vs baseline: 1.9850x; 1.2324x over previous
#include <cuda_runtime.h>

#define T_ 512
#define K_ 8
#define D_ 8
#define NB 4

static constexpr int TK = T_ * K_;

// Per-(t,k) precomputed parameters (device scratch — no allocation)
__device__ float g_Q[TK * 64];     // [tk][i*8+j]  Q = 2*inv(I+A) - I
__device__ float g_bias[TK * 8];   // [tk][j]      = -(center . Q)_j
__device__ float g_c1[TK * 8];     // [tk][d]      = -0.5/var * log2(e)
__device__ float g_lsum[TK];       // [tk]         = sum_d -0.5*ln(2*pi*var_d)*log2(e)
__device__ float g_w[TK];          // [t][k]       softmax weights

// ---------- packed f32x2 helpers ----------
typedef unsigned long long u64_t;

static __device__ __forceinline__ u64_t pk2(float lo, float hi) {
    u64_t r;
    asm("mov.b64 %0, {%1, %2};" : "=l"(r) : "f"(lo), "f"(hi));
    return r;
}
static __device__ __forceinline__ void upk2(u64_t v, float& lo, float& hi) {
    asm("mov.b64 {%0, %1}, %2;" : "=f"(lo), "=f"(hi) : "l"(v));
}
static __device__ __forceinline__ u64_t fma2_(u64_t a, u64_t b, u64_t c) {
    u64_t d;
    asm("fma.rn.f32x2 %0, %1, %2, %3;" : "=l"(d) : "l"(a), "l"(b), "l"(c));
    return d;
}
static __device__ __forceinline__ u64_t mul2_(u64_t a, u64_t b) {
    u64_t d;
    asm("mul.rn.f32x2 %0, %1, %2;" : "=l"(d) : "l"(a), "l"(b));
    return d;
}
static __device__ __forceinline__ float ex2_(float a) {
    float r;
    asm("ex2.approx.f32 %0, %1;" : "=f"(r) : "f"(a));
    return r;
}

// ============================================================================
// Precompute, warp-parallel: 8 threads per (t,k), one Gauss-Jordan row each.
// Pivot rows exchanged with shfl (width 8); bias via butterfly reduction.
// Q = (I-A)(I+A)^-1 = 2*(I+A)^-1 - I  (commuting rational functions of A);
// (I+A) has positive-definite symmetric part -> pivot-free GJ is stable.
// ============================================================================
__global__ void __launch_bounds__(256)
precompute_kernel(const float* __restrict__ centers,
                  const float* __restrict__ wlog,
                  const float* __restrict__ logvar,
                  const float* __restrict__ cov)
{
    const int gtid = blockIdx.x * 256 + threadIdx.x;
    const int tk   = gtid >> 3;     // 0 .. TK-1
    const int r    = gtid & 7;      // row owned by this thread
    if (tk >= TK) return;

    // Softmax of clipped weight logits (one lane per t, t == tk for tk < T_)
    if (tk < T_ && r == 0) {
        const int t = tk;
        float l[K_];
        float mx = -1e30f;
        #pragma unroll
        for (int k = 0; k < K_; k++) {
            float v = wlog[t * K_ + k];
            v = fminf(fmaxf(v, -3.5f), 3.5f);
            l[k] = v;
            mx = fmaxf(mx, v);
        }
        float s = 0.f;
        #pragma unroll
        for (int k = 0; k < K_; k++) { l[k] = __expf(l[k] - mx); s += l[k]; }
        float inv = 1.0f / s;
        #pragma unroll
        for (int k = 0; k < K_; k++) g_w[t * K_ + k] = l[k] * inv;
    }

    // ---- build row r of M = I + A  (A antisym from 28 cov params) ----
    // flat[j] = v[j] for j<28, v[55-j] for 28<=j<56 (tf concat [v, v[::-1]])
    const float* v = cov + tk * 28;
    float Mrow[8];
    #pragma unroll
    for (int c = 0; c < 8; c++) {
        float ut_rc = 0.f, ut_cr = 0.f;
        if (c > r) { int j = 8 * r + c; ut_rc = (j < 28) ? v[j] : v[55 - j]; }
        if (r > c) { int j = 8 * c + r; ut_cr = (j < 28) ? v[j] : v[55 - j]; }
        Mrow[c] = 0.5f * (ut_cr - ut_rc) + ((r == c) ? 1.f : 0.f);
    }

    // ---- distributed in-place Gauss-Jordan inverse, no pivoting ----
    #pragma unroll
    for (int col = 0; col < 8; col++) {
        float prow[8];
        #pragma unroll
        for (int j = 0; j < 8; j++)
            prow[j] = __shfl_sync(0xffffffffu, Mrow[j], col, 8);
        const float p = 1.0f / prow[col];
        if (r == col) {
            #pragma unroll
            for (int j = 0; j < 8; j++)
                Mrow[j] = (j == col) ? p : prow[j] * p;
        } else {
            const float f = Mrow[col];
            #pragma unroll
            for (int j = 0; j < 8; j++)
                if (j != col) Mrow[j] = fmaf(-f, prow[j] * p, Mrow[j]);
            Mrow[col] = -f * p;
        }
    }

    // ---- Q row = 2*inv(I+A) row - I row ----
    float Qrow[8];
    #pragma unroll
    for (int j = 0; j < 8; j++) {
        Qrow[j] = 2.0f * Mrow[j] - ((r == j) ? 1.f : 0.f);
        g_Q[tk * 64 + r * 8 + j] = Qrow[j];
    }

    // ---- bias_j = -(center . Q)_j : butterfly-reduce c_r * Qrow over lanes ----
    {
        const float cr = centers[tk * 8 + r];
        float s[8];
        #pragma unroll
        for (int j = 0; j < 8; j++) s[j] = cr * Qrow[j];
        #pragma unroll
        for (int m = 1; m < 8; m <<= 1) {
            #pragma unroll
            for (int j = 0; j < 8; j++)
                s[j] += __shfl_xor_sync(0xffffffffu, s[j], m, 8);
        }
        g_bias[tk * 8 + r] = -s[r];   // lane r writes element r
    }

    // ---- variance terms in log2 domain; per-(t,k) lc0 SUM (log-space mix) ----
    {
        const float LOG2PI = 1.8378770664093453f;
        const float LOG2E  = 1.4426950408889634f;
        float lv = logvar[tk * 8 + r];
        lv = fminf(fmaxf(lv, -3.5f), 3.5f);
        g_c1[tk * 8 + r] = -0.5f * expf(-lv) * LOG2E;
        float lc = -0.5f * (LOG2PI + lv) * LOG2E;
        // butterfly-sum lc over the 8 lanes of this (t,k) group
        #pragma unroll
        for (int m = 1; m < 8; m <<= 1)
            lc += __shfl_xor_sync(0xffffffffu, lc, m, 8);
        if (r == 0) g_lsum[tk] = lc;
    }
}

// ============================================================================
// Main kernel: one block per (b-chunk, t); each thread computes NB=4 outputs.
// Log-space mixture:
//   p[b,t] = sum_k ex2( sum_d c1'_d*xt_d^2  +  [sum_d lc0'_d + log2 w_k] )
// xt = x . Q + bias, packed fma.rn.f32x2 over j-pairs (x-dup packs hoisted
// by ptxas — do NOT restructure the matvec, see round-3 post-mortem).
// The +eps inside the reference's log is dropped (negligible except where the
// product itself is ~0); no underflow guard needed since no partial products.
// ============================================================================
__global__ void __launch_bounds__(128)
pecd_main_kernel(const float* __restrict__ x, float* __restrict__ out)
{
    const int t   = blockIdx.y;
    const int tid = threadIdx.x;

    __shared__ __align__(16) float sQ[K_ * 64];
    __shared__ __align__(16) float sB[K_ * 8];
    __shared__ __align__(16) float sC[K_ * 8];
    __shared__ float sLW[K_];   // lsum + log2(w_k)

    {
        const float* gq = g_Q + t * (K_ * 64);
        for (int i = tid; i < K_ * 64; i += 128) sQ[i] = gq[i];
        if (tid < 64) {
            sB[tid] = g_bias[t * 64 + tid];
            sC[tid] = g_c1[t * 64 + tid];
        }
        if (tid < K_)
            sLW[tid] = g_lsum[t * K_ + tid] + __log2f(g_w[t * K_ + tid]);
    }
    __syncthreads();

    const int b0 = blockIdx.x * (128 * NB) + tid;

    // load x rows: each (b,t) row is 8 floats = one aligned 32B sector
    float xr[NB][8];
    const float4* x4 = reinterpret_cast<const float4*>(x);
    #pragma unroll
    for (int ib = 0; ib < NB; ib++) {
        const int b = b0 + ib * 128;
        const float4 p0 = x4[(size_t)(b * T_ + t) * 2 + 0];
        const float4 p1 = x4[(size_t)(b * T_ + t) * 2 + 1];
        xr[ib][0] = p0.x; xr[ib][1] = p0.y; xr[ib][2] = p0.z; xr[ib][3] = p0.w;
        xr[ib][4] = p1.x; xr[ib][5] = p1.y; xr[ib][6] = p1.z; xr[ib][7] = p1.w;
    }

    float acc[NB];
    #pragma unroll
    for (int ib = 0; ib < NB; ib++) acc[ib] = 0.f;

    #pragma unroll
    for (int k = 0; k < K_; k++) {
        const float4* q4 = reinterpret_cast<const float4*>(&sQ[k * 64]);

        // bias pairs
        const float4 bb0 = reinterpret_cast<const float4*>(&sB[k * 8])[0];
        const float4 bb1 = reinterpret_cast<const float4*>(&sB[k * 8])[1];
        u64_t bias01 = pk2(bb0.x, bb0.y), bias23 = pk2(bb0.z, bb0.w);
        u64_t bias45 = pk2(bb1.x, bb1.y), bias67 = pk2(bb1.z, bb1.w);

        u64_t xt[NB][4];
        #pragma unroll
        for (int ib = 0; ib < NB; ib++) {
            xt[ib][0] = bias01; xt[ib][1] = bias23;
            xt[ib][2] = bias45; xt[ib][3] = bias67;
        }

        // xt_j += sum_i x_i * Q[i][j]   (packed over j-pairs)
        #pragma unroll
        for (int i = 0; i < 8; i++) {
            const float4 qa = q4[2 * i + 0];
            const float4 qb = q4[2 * i + 1];
            const u64_t q01 = pk2(qa.x, qa.y), q23 = pk2(qa.z, qa.w);
            const u64_t q45 = pk2(qb.x, qb.y), q67 = pk2(qb.z, qb.w);
            #pragma unroll
            for (int ib = 0; ib < NB; ib++) {
                const u64_t xi = pk2(xr[ib][i], xr[ib][i]);
                xt[ib][0] = fma2_(xi, q01, xt[ib][0]);
                xt[ib][1] = fma2_(xi, q23, xt[ib][1]);
                xt[ib][2] = fma2_(xi, q45, xt[ib][2]);
                xt[ib][3] = fma2_(xi, q67, xt[ib][3]);
            }
        }

        // log-space reduction: s = sum_d c1'_d * xt_d^2  (packed dot), then ex2
        const float4 c0 = reinterpret_cast<const float4*>(&sC[k * 8])[0];
        const float4 c1 = reinterpret_cast<const float4*>(&sC[k * 8])[1];
        u64_t cp[4];
        cp[0] = pk2(c0.x, c0.y); cp[1] = pk2(c0.z, c0.w);
        cp[2] = pk2(c1.x, c1.y); cp[3] = pk2(c1.z, c1.w);

        const float lw = sLW[k];

        #pragma unroll
        for (int ib = 0; ib < NB; ib++) {
            u64_t t0 = mul2_(xt[ib][0], xt[ib][0]);
            u64_t a  = mul2_(cp[0], t0);
            u64_t t1 = mul2_(xt[ib][1], xt[ib][1]);
            a = fma2_(cp[1], t1, a);
            u64_t t2 = mul2_(xt[ib][2], xt[ib][2]);
            a = fma2_(cp[2], t2, a);
            u64_t t3 = mul2_(xt[ib][3], xt[ib][3]);
            a = fma2_(cp[3], t3, a);
            float lo, hi;
            upk2(a, lo, hi);
            acc[ib] += ex2_(lo + hi + lw);
        }
    }

    #pragma unroll
    for (int ib = 0; ib < NB; ib++) {
        const int b = b0 + ib * 128;
        out[(size_t)b * T_ + t] = acc[ib];
    }
}

// ============================================================================
extern "C" void kernel_launch(void* const* d_in, const int* in_sizes, int n_in,
                              void* d_out, int out_size)
{
    const float* x       = (const float*)d_in[0];  // [B, T, D]
    const float* centers = (const float*)d_in[1];  // [T, K, D]
    const float* wlog    = (const float*)d_in[2];  // [T, K]
    const float* logvar  = (const float*)d_in[3];  // [T, K, D]
    const float* cov     = (const float*)d_in[4];  // [T, K, 28]

    const int B = in_sizes[0] / (T_ * D_);         // 2048

    precompute_kernel<<<(TK * 8) / 256, 256>>>(centers, wlog, logvar, cov);

    dim3 grid(B / (128 * NB), T_);                 // (4, 512)
    pecd_main_kernel<<<grid, 128>>>(x, (float*)d_out);
}

// round 12
// speedup vs baseline: 2.1352x; 1.0757x over previous
#include <cuda_runtime.h>

#define T_ 512
#define K_ 8
#define D_ 8
#define NB 4

static constexpr int TK = T_ * K_;

// Per-(t,k) precomputed parameters (device scratch — no allocation)
// Qs = Q * diag(s), bs = bias * s, with s_d = sqrt(0.5*exp(-lv_d)*log2e),
// so exponent(b,t,k) = lw - sum_d (x . Qs_d + bs_d)^2
__device__ float g_Qs[TK * 64];    // [tk][i*8+j]
__device__ float g_bs[TK * 8];     // [tk][j]
__device__ float g_lsum[TK];       // [tk]   = sum_d -0.5*ln(2*pi*var_d)*log2(e)
__device__ float g_w[TK];          // [t][k] softmax weights

// ---------- packed f32x2 helpers ----------
typedef unsigned long long u64_t;

static __device__ __forceinline__ u64_t pk2(float lo, float hi) {
    u64_t r;
    asm("mov.b64 %0, {%1, %2};" : "=l"(r) : "f"(lo), "f"(hi));
    return r;
}
static __device__ __forceinline__ void upk2(u64_t v, float& lo, float& hi) {
    asm("mov.b64 {%0, %1}, %2;" : "=f"(lo), "=f"(hi) : "l"(v));
}
static __device__ __forceinline__ u64_t fma2_(u64_t a, u64_t b, u64_t c) {
    u64_t d;
    asm("fma.rn.f32x2 %0, %1, %2, %3;" : "=l"(d) : "l"(a), "l"(b), "l"(c));
    return d;
}
static __device__ __forceinline__ u64_t mul2_(u64_t a, u64_t b) {
    u64_t d;
    asm("mul.rn.f32x2 %0, %1, %2;" : "=l"(d) : "l"(a), "l"(b));
    return d;
}
static __device__ __forceinline__ float ex2_(float a) {
    float r;
    asm("ex2.approx.f32 %0, %1;" : "=f"(r) : "f"(a));
    return r;
}

// ============================================================================
// Precompute, warp-parallel: 8 threads per (t,k), one Gauss-Jordan row each.
// Q = (I-A)(I+A)^-1 = 2*(I+A)^-1 - I  (commuting rational functions of A);
// (I+A) has positive-definite symmetric part -> pivot-free GJ is stable.
// Then scale column d of Q (and bias_d) by s_d = sqrt(0.5*exp(-lv_d)*log2e).
// ============================================================================
__global__ void __launch_bounds__(256)
precompute_kernel(const float* __restrict__ centers,
                  const float* __restrict__ wlog,
                  const float* __restrict__ logvar,
                  const float* __restrict__ cov)
{
    const int gtid = blockIdx.x * 256 + threadIdx.x;
    const int tk   = gtid >> 3;     // 0 .. TK-1
    const int r    = gtid & 7;      // row owned by this thread
    if (tk >= TK) return;

    // Softmax of clipped weight logits (one lane per t, t == tk for tk < T_)
    if (tk < T_ && r == 0) {
        const int t = tk;
        float l[K_];
        float mx = -1e30f;
        #pragma unroll
        for (int k = 0; k < K_; k++) {
            float v = wlog[t * K_ + k];
            v = fminf(fmaxf(v, -3.5f), 3.5f);
            l[k] = v;
            mx = fmaxf(mx, v);
        }
        float s = 0.f;
        #pragma unroll
        for (int k = 0; k < K_; k++) { l[k] = __expf(l[k] - mx); s += l[k]; }
        float inv = 1.0f / s;
        #pragma unroll
        for (int k = 0; k < K_; k++) g_w[t * K_ + k] = l[k] * inv;
    }

    // ---- build row r of M = I + A  (A antisym from 28 cov params) ----
    // flat[j] = v[j] for j<28, v[55-j] for 28<=j<56 (tf concat [v, v[::-1]])
    const float* v = cov + tk * 28;
    float Mrow[8];
    #pragma unroll
    for (int c = 0; c < 8; c++) {
        float ut_rc = 0.f, ut_cr = 0.f;
        if (c > r) { int j = 8 * r + c; ut_rc = (j < 28) ? v[j] : v[55 - j]; }
        if (r > c) { int j = 8 * c + r; ut_cr = (j < 28) ? v[j] : v[55 - j]; }
        Mrow[c] = 0.5f * (ut_cr - ut_rc) + ((r == c) ? 1.f : 0.f);
    }

    // ---- distributed in-place Gauss-Jordan inverse, no pivoting ----
    #pragma unroll
    for (int col = 0; col < 8; col++) {
        float prow[8];
        #pragma unroll
        for (int j = 0; j < 8; j++)
            prow[j] = __shfl_sync(0xffffffffu, Mrow[j], col, 8);
        const float p = 1.0f / prow[col];
        if (r == col) {
            #pragma unroll
            for (int j = 0; j < 8; j++)
                Mrow[j] = (j == col) ? p : prow[j] * p;
        } else {
            const float f = Mrow[col];
            #pragma unroll
            for (int j = 0; j < 8; j++)
                if (j != col) Mrow[j] = fmaf(-f, prow[j] * p, Mrow[j]);
            Mrow[col] = -f * p;
        }
    }

    // ---- Q row = 2*inv(I+A) row - I row ----
    float Qrow[8];
    #pragma unroll
    for (int j = 0; j < 8; j++)
        Qrow[j] = 2.0f * Mrow[j] - ((r == j) ? 1.f : 0.f);

    // ---- variance scale s_d and lsum; lane r owns dim d = r ----
    const float LOG2PI = 1.8378770664093453f;
    const float LOG2E  = 1.4426950408889634f;
    float lv = logvar[tk * 8 + r];
    lv = fminf(fmaxf(lv, -3.5f), 3.5f);
    const float s_own = sqrtf(0.5f * expf(-lv) * LOG2E);   // s_d for d == r
    {
        float lc = -0.5f * (LOG2PI + lv) * LOG2E;
        #pragma unroll
        for (int m = 1; m < 8; m <<= 1)
            lc += __shfl_xor_sync(0xffffffffu, lc, m, 8);
        if (r == 0) g_lsum[tk] = lc;
    }

    // gather all 8 column scales
    float s_all[8];
    #pragma unroll
    for (int j = 0; j < 8; j++)
        s_all[j] = __shfl_sync(0xffffffffu, s_own, j, 8);

    // ---- store scaled Qs row ----
    #pragma unroll
    for (int j = 0; j < 8; j++)
        g_Qs[tk * 64 + r * 8 + j] = Qrow[j] * s_all[j];

    // ---- bias_j = -(center . Q)_j, scaled: bs_j = bias_j * s_j ----
    {
        const float cr = centers[tk * 8 + r];
        float s[8];
        #pragma unroll
        for (int j = 0; j < 8; j++) s[j] = cr * Qrow[j];
        #pragma unroll
        for (int m = 1; m < 8; m <<= 1) {
            #pragma unroll
            for (int j = 0; j < 8; j++)
                s[j] += __shfl_xor_sync(0xffffffffu, s[j], m, 8);
        }
        g_bs[tk * 8 + r] = -s[r] * s_own;   // lane r writes element r
    }
}

// ============================================================================
// Main kernel: one block per (b-chunk, t); each thread computes NB=4 outputs.
//   p[b,t] = sum_k ex2( lw_k - sum_d z_d^2 ),  z = x . Qs + bs
// Matvec packed fma.rn.f32x2 over j-pairs (x-dup packs hoisted by ptxas —
// do NOT restructure the matvec, see round-3 post-mortem). Squares accumulate
// directly via fma2(z,z,a): the c1 dot is folded into Qs/bs at precompute.
// ============================================================================
__global__ void __launch_bounds__(128, 5)
pecd_main_kernel(const float* __restrict__ x, float* __restrict__ out)
{
    const int t   = blockIdx.y;
    const int tid = threadIdx.x;

    __shared__ __align__(16) float sQ[K_ * 64];
    __shared__ __align__(16) float sB[K_ * 8];
    __shared__ float sLW[K_];   // lsum + log2(w_k)

    {
        const float* gq = g_Qs + t * (K_ * 64);
        for (int i = tid; i < K_ * 64; i += 128) sQ[i] = gq[i];
        if (tid < 64) sB[tid] = g_bs[t * 64 + tid];
        if (tid < K_)
            sLW[tid] = g_lsum[t * K_ + tid] + __log2f(g_w[t * K_ + tid]);
    }
    __syncthreads();

    const int b0 = blockIdx.x * (128 * NB) + tid;

    // load x rows: each (b,t) row is 8 floats = one aligned 32B sector
    float xr[NB][8];
    const float4* x4 = reinterpret_cast<const float4*>(x);
    #pragma unroll
    for (int ib = 0; ib < NB; ib++) {
        const int b = b0 + ib * 128;
        const float4 p0 = x4[(size_t)(b * T_ + t) * 2 + 0];
        const float4 p1 = x4[(size_t)(b * T_ + t) * 2 + 1];
        xr[ib][0] = p0.x; xr[ib][1] = p0.y; xr[ib][2] = p0.z; xr[ib][3] = p0.w;
        xr[ib][4] = p1.x; xr[ib][5] = p1.y; xr[ib][6] = p1.z; xr[ib][7] = p1.w;
    }

    float acc[NB];
    #pragma unroll
    for (int ib = 0; ib < NB; ib++) acc[ib] = 0.f;

    #pragma unroll
    for (int k = 0; k < K_; k++) {
        const float4* q4 = reinterpret_cast<const float4*>(&sQ[k * 64]);

        // bias pairs
        const float4 bb0 = reinterpret_cast<const float4*>(&sB[k * 8])[0];
        const float4 bb1 = reinterpret_cast<const float4*>(&sB[k * 8])[1];
        u64_t bias01 = pk2(bb0.x, bb0.y), bias23 = pk2(bb0.z, bb0.w);
        u64_t bias45 = pk2(bb1.x, bb1.y), bias67 = pk2(bb1.z, bb1.w);

        u64_t xt[NB][4];
        #pragma unroll
        for (int ib = 0; ib < NB; ib++) {
            xt[ib][0] = bias01; xt[ib][1] = bias23;
            xt[ib][2] = bias45; xt[ib][3] = bias67;
        }

        // z_j += sum_i x_i * Qs[i][j]   (packed over j-pairs)
        #pragma unroll
        for (int i = 0; i < 8; i++) {
            const float4 qa = q4[2 * i + 0];
            const float4 qb = q4[2 * i + 1];
            const u64_t q01 = pk2(qa.x, qa.y), q23 = pk2(qa.z, qa.w);
            const u64_t q45 = pk2(qb.x, qb.y), q67 = pk2(qb.z, qb.w);
            #pragma unroll
            for (int ib = 0; ib < NB; ib++) {
                const u64_t xi = pk2(xr[ib][i], xr[ib][i]);
                xt[ib][0] = fma2_(xi, q01, xt[ib][0]);
                xt[ib][1] = fma2_(xi, q23, xt[ib][1]);
                xt[ib][2] = fma2_(xi, q45, xt[ib][2]);
                xt[ib][3] = fma2_(xi, q67, xt[ib][3]);
            }
        }

        const float lw = sLW[k];

        // exponent = lw - sum_d z_d^2 ; squares accumulate via fma2
        #pragma unroll
        for (int ib = 0; ib < NB; ib++) {
            u64_t a = mul2_(xt[ib][0], xt[ib][0]);
            a = fma2_(xt[ib][1], xt[ib][1], a);
            a = fma2_(xt[ib][2], xt[ib][2], a);
            a = fma2_(xt[ib][3], xt[ib][3], a);
            float lo, hi;
            upk2(a, lo, hi);
            acc[ib] += ex2_(lw - lo - hi);
        }
    }

    #pragma unroll
    for (int ib = 0; ib < NB; ib++) {
        const int b = b0 + ib * 128;
        out[(size_t)b * T_ + t] = acc[ib];
    }
}

// ============================================================================
extern "C" void kernel_launch(void* const* d_in, const int* in_sizes, int n_in,
                              void* d_out, int out_size)
{
    const float* x       = (const float*)d_in[0];  // [B, T, D]
    const float* centers = (const float*)d_in[1];  // [T, K, D]
    const float* wlog    = (const float*)d_in[2];  // [T, K]
    const float* logvar  = (const float*)d_in[3];  // [T, K, D]
    const float* cov     = (const float*)d_in[4];  // [T, K, 28]

    const int B = in_sizes[0] / (T_ * D_);         // 2048

    precompute_kernel<<<(TK * 8) / 256, 256>>>(centers, wlog, logvar, cov);

    dim3 grid(B / (128 * NB), T_);                 // (4, 512)
    pecd_main_kernel<<<grid, 128>>>(x, (float*)d_out);
}